// round 8
// baseline (speedup 1.0000x reference)
#include <cuda_runtime.h>

#define NN 50000
#define EE 800000
#define DD 64
#define NB 196   // (NN + 255) / 256 scan blocks

// Scratch (device globals — allocation-free per harness rules)
__device__ __align__(16) float g_agg[NN * DD];   // mean-aggregated features (reused both layers)
__device__ __align__(16) float g_h[NN * DD];     // layer-1 output
__device__ int g_src32[EE];
__device__ int g_dst32[EE];
__device__ int g_deg[NN];
__device__ int g_loc[NN];       // per-element exclusive scan within its block
__device__ int g_bsum[NB];      // per-block degree sums
__device__ int g_bbase[NB];     // exclusive scan of block sums
__device__ int g_off[NN + 1];
__device__ int g_cur[NN];
__device__ int g_csr_src[EE];
__device__ int g_is64;

// ---------------------------------------------------------------------------
// Kernel 0: fused init — zero degree counts everywhere; block 0 additionally
// detects edge_index dtype (int64 => odd 32-bit words all zero, 64 probes).
// ---------------------------------------------------------------------------
__global__ __launch_bounds__(256) void init_kernel(const int* __restrict__ ei32) {
    int t = blockIdx.x * 256 + threadIdx.x;
    if (t < NN) g_deg[t] = 0;
    if (blockIdx.x == 0) {
        __shared__ int any_nz;
        if (threadIdx.x == 0) any_nz = 0;
        __syncthreads();
        if (threadIdx.x < 64 && ei32[2 * threadIdx.x + 1] != 0) atomicOr(&any_nz, 1);
        __syncthreads();
        if (threadIdx.x == 0) g_is64 = !any_nz;
    }
}

// ---------------------------------------------------------------------------
// Kernel 1: normalize indices to int32 + integer degree histogram
// ---------------------------------------------------------------------------
__global__ __launch_bounds__(256) void convert_kernel(const void* __restrict__ ei) {
    int e = blockIdx.x * blockDim.x + threadIdx.x;
    if (e >= EE) return;
    int s, d;
    if (g_is64) {
        const long long* p = (const long long*)ei;
        s = (int)p[e];
        d = (int)p[EE + e];
    } else {
        const int* p = (const int*)ei;
        s = p[e];
        d = p[EE + e];
    }
    s = min(max(s, 0), NN - 1);
    d = min(max(d, 0), NN - 1);
    g_src32[e] = s;
    g_dst32[e] = d;
    atomicAdd(&g_deg[d], 1);
}

// ---------------------------------------------------------------------------
// Kernels 2a/2b/2c: 3-phase multi-block exclusive scan of g_deg -> g_off.
// ---------------------------------------------------------------------------
__global__ __launch_bounds__(256) void scan1_kernel() {
    __shared__ int sh[256];
    int tid = threadIdx.x;
    int i = blockIdx.x * 256 + tid;
    int v = (i < NN) ? g_deg[i] : 0;
    sh[tid] = v;
    __syncthreads();
    #pragma unroll
    for (int d = 1; d < 256; d <<= 1) {
        int t = (tid >= d) ? sh[tid - d] : 0;
        __syncthreads();
        sh[tid] += t;
        __syncthreads();
    }
    if (i < NN) g_loc[i] = sh[tid] - v;          // exclusive within block
    if (tid == 255) g_bsum[blockIdx.x] = sh[255]; // block total
}

__global__ __launch_bounds__(256) void scan2_kernel() {
    __shared__ int sh[256];
    int tid = threadIdx.x;
    int v = (tid < NB) ? g_bsum[tid] : 0;
    sh[tid] = v;
    __syncthreads();
    #pragma unroll
    for (int d = 1; d < 256; d <<= 1) {
        int t = (tid >= d) ? sh[tid - d] : 0;
        __syncthreads();
        sh[tid] += t;
        __syncthreads();
    }
    if (tid < NB) g_bbase[tid] = sh[tid] - v;    // exclusive block base
}

__global__ __launch_bounds__(256) void scan3_kernel() {
    int i = blockIdx.x * 256 + threadIdx.x;
    if (i < NN) {
        int off = g_loc[i] + g_bbase[blockIdx.x];
        g_off[i] = off;
        g_cur[i] = off;
    }
    if (i == 0) g_off[NN] = EE;
}

// ---------------------------------------------------------------------------
// Kernel 3: CSR fill (source indices grouped by destination)
// ---------------------------------------------------------------------------
__global__ __launch_bounds__(256) void fill_kernel() {
    int e = blockIdx.x * blockDim.x + threadIdx.x;
    if (e >= EE) return;
    int d = g_dst32[e];
    int pos = atomicAdd(&g_cur[d], 1);
    g_csr_src[pos] = g_src32[e];
}

// ---------------------------------------------------------------------------
// Kernel 4/6: gather-based mean aggregation. One warp per node; lanes 0-15
// handle one edge's row (float4 each), lanes 16-31 the next edge. Inner loop
// unrolled x4 (8 edges in flight per warp) with two independent accumulators
// to hide L2 latency. No atomics. Writes mean into g_agg.
// ---------------------------------------------------------------------------
template <int LAYER>
__global__ __launch_bounds__(256) void gather_kernel(const float* __restrict__ xext)
{
    int n = (blockIdx.x * 256 + threadIdx.x) >> 5;
    if (n >= NN) return;
    int lane = threadIdx.x & 31;
    int half = lane >> 4;        // 0 or 1
    int fl   = lane & 15;        // feature float4 index

    const float* xin = (LAYER == 1) ? xext : g_h;

    int beg = g_off[n];
    int end = g_off[n + 1];

    float4 a0 = make_float4(0.f, 0.f, 0.f, 0.f);
    float4 a1 = make_float4(0.f, 0.f, 0.f, 0.f);

    int e = beg + half;
    // Unrolled: this half consumes edges e, e+2, e+4, e+6 per iteration.
    for (; e + 6 < end; e += 8) {
        int s0 = g_csr_src[e];
        int s1 = g_csr_src[e + 2];
        int s2 = g_csr_src[e + 4];
        int s3 = g_csr_src[e + 6];
        float4 v0 = *reinterpret_cast<const float4*>(xin + (size_t)s0 * DD + (fl << 2));
        float4 v1 = *reinterpret_cast<const float4*>(xin + (size_t)s1 * DD + (fl << 2));
        float4 v2 = *reinterpret_cast<const float4*>(xin + (size_t)s2 * DD + (fl << 2));
        float4 v3 = *reinterpret_cast<const float4*>(xin + (size_t)s3 * DD + (fl << 2));
        a0.x += v0.x; a0.y += v0.y; a0.z += v0.z; a0.w += v0.w;
        a1.x += v1.x; a1.y += v1.y; a1.z += v1.z; a1.w += v1.w;
        a0.x += v2.x; a0.y += v2.y; a0.z += v2.z; a0.w += v2.w;
        a1.x += v3.x; a1.y += v3.y; a1.z += v3.z; a1.w += v3.w;
    }
    for (; e < end; e += 2) {
        int s = g_csr_src[e];
        float4 v = *reinterpret_cast<const float4*>(xin + (size_t)s * DD + (fl << 2));
        a0.x += v.x; a0.y += v.y; a0.z += v.z; a0.w += v.w;
    }
    a0.x += a1.x; a0.y += a1.y; a0.z += a1.z; a0.w += a1.w;

    // combine the two halves
    a0.x += __shfl_xor_sync(0xFFFFFFFF, a0.x, 16);
    a0.y += __shfl_xor_sync(0xFFFFFFFF, a0.y, 16);
    a0.z += __shfl_xor_sync(0xFFFFFFFF, a0.z, 16);
    a0.w += __shfl_xor_sync(0xFFFFFFFF, a0.w, 16);

    if (half == 0) {
        float inv = 1.0f / (float)max(end - beg, 1);
        a0.x *= inv; a0.y *= inv; a0.z *= inv; a0.w *= inv;
        *reinterpret_cast<float4*>(g_agg + (size_t)n * DD + (fl << 2)) = a0;
    }
}

// ---------------------------------------------------------------------------
// Kernel 5/7: register-tiled fused MLP (dynamic smem, ~64.3 KB/block).
//   out[n][j] = sum_k I[n][k] * Wc[k][j] + b[j]   (+ tanh for layer 1)
// where I = [agg | x] (K=128) and Wc = [W_l^T ; W_r^T] (128 x 64, k-major).
// Block tile: 64 nodes x 64 outputs; thread = 4x4 micro-tile; 2 B LDS per FMA.
// ---------------------------------------------------------------------------
#define MLP_SMEM_BYTES ((2 * DD * DD + 2 * DD * DD + DD) * 4)

template <int LAYER>
__global__ __launch_bounds__(256) void mlp_kernel(
    const float* __restrict__ xext,
    const float* __restrict__ Wl,
    const float* __restrict__ bl,
    const float* __restrict__ Wr,
    float* __restrict__ outext)
{
    const float* xin = (LAYER == 1) ? xext : g_h;
    float*       out = (LAYER == 1) ? g_h : outext;

    extern __shared__ float smem[];
    float* sW = smem;                     // 8192 floats
    float* sI = smem + 2 * DD * DD;       // 8192 floats
    float* sB = sI + 2 * DD * DD;         // 64 floats

    // Stage combined weights, k-major transposed
    for (int t = threadIdx.x; t < DD * DD; t += 256) {
        int j = t >> 6, k = t & 63;
        sW[k * DD + j]        = Wl[t];
        sW[(DD + k) * DD + j] = Wr[t];
    }
    if (threadIdx.x < DD) sB[threadIdx.x] = bl[threadIdx.x];

    const int ty = threadIdx.x >> 4;       // 0..15 -> node group
    const int tx = threadIdx.x & 15;       // 0..15 -> output group
    const int n0 = ty << 2;
    const int j0 = tx << 2;
    const int ngroups = (NN + 63) / 64;    // 782

    for (int g = blockIdx.x; g < ngroups; g += gridDim.x) {
        int base = g << 6;
        __syncthreads();
        // Stage [agg|x] transposed: t = q*64 + node, q in [0,32)
        for (int t = threadIdx.x; t < 32 * 64; t += 256) {
            int q    = t >> 6;        // which float4 within the combined 128-dim row
            int node = t & 63;
            int ni   = base + node;
            float4 v = make_float4(0.f, 0.f, 0.f, 0.f);
            int kbase;
            if (q < 16) {
                kbase = q << 2;
                if (ni < NN) v = reinterpret_cast<const float4*>(g_agg + (size_t)ni * DD)[q];
            } else {
                kbase = DD + ((q - 16) << 2);
                if (ni < NN) v = reinterpret_cast<const float4*>(xin + (size_t)ni * DD)[q - 16];
            }
            sI[(kbase + 0) * DD + node] = v.x;
            sI[(kbase + 1) * DD + node] = v.y;
            sI[(kbase + 2) * DD + node] = v.z;
            sI[(kbase + 3) * DD + node] = v.w;
        }
        __syncthreads();

        float acc[4][4];
        #pragma unroll
        for (int i = 0; i < 4; i++)
            #pragma unroll
            for (int j = 0; j < 4; j++) acc[i][j] = 0.f;

        #pragma unroll 4
        for (int k = 0; k < 2 * DD; k++) {
            float4 a = *reinterpret_cast<const float4*>(sI + k * DD + n0);
            float4 w = *reinterpret_cast<const float4*>(sW + k * DD + j0);
            acc[0][0] += a.x * w.x; acc[0][1] += a.x * w.y; acc[0][2] += a.x * w.z; acc[0][3] += a.x * w.w;
            acc[1][0] += a.y * w.x; acc[1][1] += a.y * w.y; acc[1][2] += a.y * w.z; acc[1][3] += a.y * w.w;
            acc[2][0] += a.z * w.x; acc[2][1] += a.z * w.y; acc[2][2] += a.z * w.z; acc[2][3] += a.z * w.w;
            acc[3][0] += a.w * w.x; acc[3][1] += a.w * w.y; acc[3][2] += a.w * w.z; acc[3][3] += a.w * w.w;
        }

        float4 b4 = *reinterpret_cast<const float4*>(sB + j0);
        #pragma unroll
        for (int i = 0; i < 4; i++) {
            int ni = base + n0 + i;
            if (ni < NN) {
                float4 o;
                o.x = acc[i][0] + b4.x;
                o.y = acc[i][1] + b4.y;
                o.z = acc[i][2] + b4.z;
                o.w = acc[i][3] + b4.w;
                if (LAYER == 1) {
                    o.x = tanhf(o.x); o.y = tanhf(o.y);
                    o.z = tanhf(o.z); o.w = tanhf(o.w);
                }
                *reinterpret_cast<float4*>(out + (size_t)ni * DD + j0) = o;
            }
        }
    }
}

// ---------------------------------------------------------------------------
// Launch
// ---------------------------------------------------------------------------
extern "C" void kernel_launch(void* const* d_in, const int* in_sizes, int n_in,
                              void* d_out, int out_size)
{
    const float* x    = (const float*)d_in[0];
    const void*  ei   = d_in[1];
    const float* Wl1  = (const float*)d_in[2];
    const float* bl1  = (const float*)d_in[3];
    const float* Wr1  = (const float*)d_in[4];
    const float* Wl2  = (const float*)d_in[5];
    const float* bl2  = (const float*)d_in[6];
    const float* Wr2  = (const float*)d_in[7];
    float*       out  = (float*)d_out;

    // Opt in to >48KB dynamic smem (immediate API, capture-safe, idempotent)
    static int attr_done = 0;
    if (!attr_done) {
        cudaFuncSetAttribute(mlp_kernel<1>,
            cudaFuncAttributeMaxDynamicSharedMemorySize, MLP_SMEM_BYTES);
        cudaFuncSetAttribute(mlp_kernel<2>,
            cudaFuncAttributeMaxDynamicSharedMemorySize, MLP_SMEM_BYTES);
        attr_done = 1;
    }

    const int eb  = (EE + 255) / 256;          // edge-parallel blocks
    const int gb  = (NN * 32 + 255) / 256;     // gather: warp per node
    const int mb  = 444;                       // mlp: 3 resident blocks/SM

    init_kernel<<<NB, 256>>>((const int*)ei);
    convert_kernel<<<eb, 256>>>(ei);
    scan1_kernel<<<NB, 256>>>();
    scan2_kernel<<<1, 256>>>();
    scan3_kernel<<<NB, 256>>>();
    fill_kernel<<<eb, 256>>>();
    gather_kernel<1><<<gb, 256>>>(x);
    mlp_kernel<1><<<mb, 256, MLP_SMEM_BYTES>>>(x, Wl1, bl1, Wr1, nullptr);
    gather_kernel<2><<<gb, 256>>>(nullptr);
    mlp_kernel<2><<<mb, 256, MLP_SMEM_BYTES>>>(nullptr, Wl2, bl2, Wr2, out);
}

// round 9
// speedup vs baseline: 1.0397x; 1.0397x over previous
#include <cuda_runtime.h>

#define NN 50000
#define EE 800000
#define DD 64
#define NB 196   // (NN + 255) / 256 scan blocks
#define RP 132   // sI row pitch in floats (128 + 4 pad)

// Scratch (device globals — allocation-free per harness rules)
__device__ __align__(16) float g_h[NN * DD];     // layer-1 output
__device__ int g_src32[EE];
__device__ int g_dst32[EE];
__device__ int g_deg[NN];
__device__ int g_loc[NN];       // per-element exclusive scan within its block
__device__ int g_bsum[NB];      // per-block degree sums
__device__ int g_bbase[NB];     // exclusive scan of block sums
__device__ int g_off[NN + 1];
__device__ int g_cur[NN];
__device__ int g_csr_src[EE];
__device__ int g_is64;

// ---------------------------------------------------------------------------
// Kernel 0: fused init — zero degree counts everywhere; block 0 additionally
// detects edge_index dtype (int64 => odd 32-bit words all zero, 64 probes).
// ---------------------------------------------------------------------------
__global__ __launch_bounds__(256) void init_kernel(const int* __restrict__ ei32) {
    int t = blockIdx.x * 256 + threadIdx.x;
    if (t < NN) g_deg[t] = 0;
    if (blockIdx.x == 0) {
        __shared__ int any_nz;
        if (threadIdx.x == 0) any_nz = 0;
        __syncthreads();
        if (threadIdx.x < 64 && ei32[2 * threadIdx.x + 1] != 0) atomicOr(&any_nz, 1);
        __syncthreads();
        if (threadIdx.x == 0) g_is64 = !any_nz;
    }
}

// ---------------------------------------------------------------------------
// Kernel 1: normalize indices to int32 + integer degree histogram
// ---------------------------------------------------------------------------
__global__ __launch_bounds__(256) void convert_kernel(const void* __restrict__ ei) {
    int e = blockIdx.x * blockDim.x + threadIdx.x;
    if (e >= EE) return;
    int s, d;
    if (g_is64) {
        const long long* p = (const long long*)ei;
        s = (int)p[e];
        d = (int)p[EE + e];
    } else {
        const int* p = (const int*)ei;
        s = p[e];
        d = p[EE + e];
    }
    s = min(max(s, 0), NN - 1);
    d = min(max(d, 0), NN - 1);
    g_src32[e] = s;
    g_dst32[e] = d;
    atomicAdd(&g_deg[d], 1);
}

// ---------------------------------------------------------------------------
// Kernels 2a/2b/2c: 3-phase multi-block exclusive scan of g_deg -> g_off.
// ---------------------------------------------------------------------------
__global__ __launch_bounds__(256) void scan1_kernel() {
    __shared__ int sh[256];
    int tid = threadIdx.x;
    int i = blockIdx.x * 256 + tid;
    int v = (i < NN) ? g_deg[i] : 0;
    sh[tid] = v;
    __syncthreads();
    #pragma unroll
    for (int d = 1; d < 256; d <<= 1) {
        int t = (tid >= d) ? sh[tid - d] : 0;
        __syncthreads();
        sh[tid] += t;
        __syncthreads();
    }
    if (i < NN) g_loc[i] = sh[tid] - v;          // exclusive within block
    if (tid == 255) g_bsum[blockIdx.x] = sh[255]; // block total
}

__global__ __launch_bounds__(256) void scan2_kernel() {
    __shared__ int sh[256];
    int tid = threadIdx.x;
    int v = (tid < NB) ? g_bsum[tid] : 0;
    sh[tid] = v;
    __syncthreads();
    #pragma unroll
    for (int d = 1; d < 256; d <<= 1) {
        int t = (tid >= d) ? sh[tid - d] : 0;
        __syncthreads();
        sh[tid] += t;
        __syncthreads();
    }
    if (tid < NB) g_bbase[tid] = sh[tid] - v;    // exclusive block base
}

__global__ __launch_bounds__(256) void scan3_kernel() {
    int i = blockIdx.x * 256 + threadIdx.x;
    if (i < NN) {
        int off = g_loc[i] + g_bbase[blockIdx.x];
        g_off[i] = off;
        g_cur[i] = off;
    }
    if (i == 0) g_off[NN] = EE;
}

// ---------------------------------------------------------------------------
// Kernel 3: CSR fill (source indices grouped by destination)
// ---------------------------------------------------------------------------
__global__ __launch_bounds__(256) void fill_kernel() {
    int e = blockIdx.x * blockDim.x + threadIdx.x;
    if (e >= EE) return;
    int d = g_dst32[e];
    int pos = atomicAdd(&g_cur[d], 1);
    g_csr_src[pos] = g_src32[e];
}

// ---------------------------------------------------------------------------
// Kernel 4/5: FUSED aggregation + MLP.
//   out[n][j] = sum_k I[n][k]*Wc[k][j] + b[j]   (+ tanh for layer 1)
// where I[n] = [ mean_{s in N(n)} xin[s] | xin[n] ]  (K=128), built in-block:
// half-warp per node gathers neighbor rows (16 lanes x 16B = 256B coalesced),
// accumulates in registers, STS.128 directly into node-major sI (pitch RP).
// Compute: 64x64 block tile, 4x4 micro-tile/thread, FMA-bound.
// Smem: sW 32KB (k-major combined [W_l^T;W_r^T]) + sI 64*RP*4B + sB.
// ---------------------------------------------------------------------------
#define MLP_SMEM_BYTES ((2 * DD * DD + 64 * RP + DD) * 4)

template <int LAYER>
__global__ __launch_bounds__(256) void fused_kernel(
    const float* __restrict__ xext,
    const float* __restrict__ Wl,
    const float* __restrict__ bl,
    const float* __restrict__ Wr,
    float* __restrict__ outext)
{
    const float* xin = (LAYER == 1) ? xext : g_h;
    float*       out = (LAYER == 1) ? g_h : outext;

    extern __shared__ float smem[];
    float* sW = smem;                 // 8192 floats: sW[k*64 + j]
    float* sI = smem + 2 * DD * DD;   // 64 * RP floats: sI[node*RP + k]
    float* sB = sI + 64 * RP;         // 64 floats

    // Stage combined weights, k-major transposed
    for (int t = threadIdx.x; t < DD * DD; t += 256) {
        int j = t >> 6, k = t & 63;
        sW[k * DD + j]        = Wl[t];
        sW[(DD + k) * DD + j] = Wr[t];
    }
    if (threadIdx.x < DD) sB[threadIdx.x] = bl[threadIdx.x];

    const int wid  = threadIdx.x >> 5;      // warp 0..7
    const int lane = threadIdx.x & 31;
    const int half = lane >> 4;             // 0/1: which node of the pair
    const int fl   = lane & 15;             // feature float4 index

    const int ty = threadIdx.x >> 4;        // 0..15 -> node group (compute)
    const int tx = threadIdx.x & 15;        // 0..15 -> output group
    const int n0 = ty << 2;
    const int j0 = tx << 2;
    const int ngroups = (NN + 63) / 64;     // 782

    for (int g = blockIdx.x; g < ngroups; g += gridDim.x) {
        int base = g << 6;
        __syncthreads();   // smem reuse from previous group

        // ---- Gather + stage: each half-warp owns 4 nodes ----
        #pragma unroll 1
        for (int p = 0; p < 4; p++) {
            int node = (wid << 3) + (p << 1) + half;  // 0..63
            int ni = base + node;
            int beg = 0, end = 0;
            if (ni < NN) { beg = g_off[ni]; end = g_off[ni + 1]; }

            float4 a0 = make_float4(0.f, 0.f, 0.f, 0.f);
            float4 a1 = make_float4(0.f, 0.f, 0.f, 0.f);
            int e = beg;
            for (; e + 1 < end; e += 2) {
                int s0 = g_csr_src[e];
                int s1 = g_csr_src[e + 1];
                float4 v0 = *reinterpret_cast<const float4*>(xin + (size_t)s0 * DD + (fl << 2));
                float4 v1 = *reinterpret_cast<const float4*>(xin + (size_t)s1 * DD + (fl << 2));
                a0.x += v0.x; a0.y += v0.y; a0.z += v0.z; a0.w += v0.w;
                a1.x += v1.x; a1.y += v1.y; a1.z += v1.z; a1.w += v1.w;
            }
            if (e < end) {
                int s = g_csr_src[e];
                float4 v = *reinterpret_cast<const float4*>(xin + (size_t)s * DD + (fl << 2));
                a0.x += v.x; a0.y += v.y; a0.z += v.z; a0.w += v.w;
            }
            float inv = 1.0f / (float)max(end - beg, 1);
            a0.x = (a0.x + a1.x) * inv;
            a0.y = (a0.y + a1.y) * inv;
            a0.z = (a0.z + a1.z) * inv;
            a0.w = (a0.w + a1.w) * inv;
            *reinterpret_cast<float4*>(sI + node * RP + (fl << 2)) = a0;

            float4 xv = make_float4(0.f, 0.f, 0.f, 0.f);
            if (ni < NN)
                xv = *reinterpret_cast<const float4*>(xin + (size_t)ni * DD + (fl << 2));
            *reinterpret_cast<float4*>(sI + node * RP + DD + (fl << 2)) = xv;
        }
        __syncthreads();

        // ---- Compute: 4x4 micro-tile per thread ----
        float acc[4][4];
        #pragma unroll
        for (int i = 0; i < 4; i++)
            #pragma unroll
            for (int j = 0; j < 4; j++) acc[i][j] = 0.f;

        const float* r0 = sI + (n0 + 0) * RP;
        const float* r1 = sI + (n0 + 1) * RP;
        const float* r2 = sI + (n0 + 2) * RP;
        const float* r3 = sI + (n0 + 3) * RP;

        #pragma unroll 4
        for (int k = 0; k < 2 * DD; k++) {
            float4 w = *reinterpret_cast<const float4*>(sW + k * DD + j0);
            float a0v = r0[k], a1v = r1[k], a2v = r2[k], a3v = r3[k];
            acc[0][0] += a0v * w.x; acc[0][1] += a0v * w.y; acc[0][2] += a0v * w.z; acc[0][3] += a0v * w.w;
            acc[1][0] += a1v * w.x; acc[1][1] += a1v * w.y; acc[1][2] += a1v * w.z; acc[1][3] += a1v * w.w;
            acc[2][0] += a2v * w.x; acc[2][1] += a2v * w.y; acc[2][2] += a2v * w.z; acc[2][3] += a2v * w.w;
            acc[3][0] += a3v * w.x; acc[3][1] += a3v * w.y; acc[3][2] += a3v * w.z; acc[3][3] += a3v * w.w;
        }

        float4 b4 = *reinterpret_cast<const float4*>(sB + j0);
        #pragma unroll
        for (int i = 0; i < 4; i++) {
            int ni = base + n0 + i;
            if (ni < NN) {
                float4 o;
                o.x = acc[i][0] + b4.x;
                o.y = acc[i][1] + b4.y;
                o.z = acc[i][2] + b4.z;
                o.w = acc[i][3] + b4.w;
                if (LAYER == 1) {
                    o.x = tanhf(o.x); o.y = tanhf(o.y);
                    o.z = tanhf(o.z); o.w = tanhf(o.w);
                }
                *reinterpret_cast<float4*>(out + (size_t)ni * DD + j0) = o;
            }
        }
    }
}

// ---------------------------------------------------------------------------
// Launch
// ---------------------------------------------------------------------------
extern "C" void kernel_launch(void* const* d_in, const int* in_sizes, int n_in,
                              void* d_out, int out_size)
{
    const float* x    = (const float*)d_in[0];
    const void*  ei   = d_in[1];
    const float* Wl1  = (const float*)d_in[2];
    const float* bl1  = (const float*)d_in[3];
    const float* Wr1  = (const float*)d_in[4];
    const float* Wl2  = (const float*)d_in[5];
    const float* bl2  = (const float*)d_in[6];
    const float* Wr2  = (const float*)d_in[7];
    float*       out  = (float*)d_out;

    // Opt in to >48KB dynamic smem (immediate API, capture-safe, idempotent)
    static int attr_done = 0;
    if (!attr_done) {
        cudaFuncSetAttribute(fused_kernel<1>,
            cudaFuncAttributeMaxDynamicSharedMemorySize, MLP_SMEM_BYTES);
        cudaFuncSetAttribute(fused_kernel<2>,
            cudaFuncAttributeMaxDynamicSharedMemorySize, MLP_SMEM_BYTES);
        attr_done = 1;
    }

    const int eb = (EE + 255) / 256;   // edge-parallel blocks
    const int fb = 444;                // fused: 3 resident blocks/SM

    init_kernel<<<NB, 256>>>((const int*)ei);
    convert_kernel<<<eb, 256>>>(ei);
    scan1_kernel<<<NB, 256>>>();
    scan2_kernel<<<1, 256>>>();
    scan3_kernel<<<NB, 256>>>();
    fill_kernel<<<eb, 256>>>();
    fused_kernel<1><<<fb, 256, MLP_SMEM_BYTES>>>(x, Wl1, bl1, Wr1, nullptr);
    fused_kernel<2><<<fb, 256, MLP_SMEM_BYTES>>>(nullptr, Wl2, bl2, Wr2, out);
}